// round 15
// baseline (speedup 1.0000x reference)
#include <cuda_runtime.h>
#include <cstdint>

// ---------------------------------------------------------------------------
// EAM energy/forces/virial.
//   out[0]          = energy  (sum F + sum phi*mask)
//   out[1 .. 3N]    = forces  [N,3]
//   out[out_size-1] = virial  (-0.5 * sum coeff*r)
//
// Numerics (R1-R14 forensics): reference is f32; candidates for the r^2
// rounding pattern tried so far: pure-rn (x2+y2)+z2 [err 1.6266e-3],
// fma(z,fma(y,x2)) [1.7827e-3], fma(z,fma(x,y*y)) [1.8161e-3 == nvcc's own
// contraction, bit-verified vs R1]. Error is pure bulk ~ sqrt(p_mismatch);
// reference is CLOSEST to pure-rn => XLA:CPU SIMD split-half reduction:
//   lanes [x2,y2,z2,0] -> low+high = [x2+z2, y2] -> final add
//   r2 = rn( rn(x2 + z2) + y2 ),  products rounded, no FMA.
// Everything else: f32-rn ops (no FMA), IEEE sqrt/div, mask r<6,
// frac from the ROUNDED product (confirmed by R9), f64 output accumulators.
// ---------------------------------------------------------------------------

#define MAXN     100000
#define MAXPAIR  (2 * 2 * 8192)

#define RCLIP_F   ((float)(6.0 * (1.0 - 1e-7)))   // f32(5.9999994)
#define ONE_M_EPS ((float)(1.0 - 1e-7))

// Scratch (__device__ globals; no allocations allowed)
__device__ float4 g_xyzt[MAXN];     // x,y,z, type-as-bits
__device__ float4 g_force[MAXN];    // accumulated forces (w unused)
__device__ float  g_rho[MAXN];
__device__ float  g_dF[MAXN];
__device__ float2 g_pair2[MAXPAIR]; // (pair, pair_deriv) interleaved
__device__ double g_acc[2];         // [0]=energy, [1]=sum coeff*r

// ---------------------------------------------------------------------------
__device__ __forceinline__ float warp_sum(float v) {
#pragma unroll
    for (int o = 16; o > 0; o >>= 1) v += __shfl_down_sync(0xffffffffu, v, o);
    return v;
}

__device__ __forceinline__ double warp_sumd(double v) {
#pragma unroll
    for (int o = 16; o > 0; o >>= 1) v += __shfl_down_sync(0xffffffffu, v, o);
    return v;
}

__device__ __forceinline__ void red_add_v4(float4* p, float x, float y, float z) {
    asm volatile("red.global.add.v4.f32 [%0], {%1, %2, %3, %4};"
                 :: "l"(p), "f"(x), "f"(y), "f"(z), "f"(0.0f) : "memory");
}

// f32 IEEE lerp, no FMA contraction:  a + f*(b-a)
__device__ __forceinline__ float lerp_rn(float a, float b, float f) {
    return __fadd_rn(a, __fmul_rn(f, __fsub_rn(b, a)));
}

// minimum-image:  d - rint(d/10)*10  (t*10 exact; subtraction exact)
__device__ __forceinline__ float minimg(float d) {
    float t = rintf(__fdiv_rn(d, 10.0f));
    return __fsub_rn(d, __fmul_rn(t, 10.0f));
}

// Split-half SIMD association:  r2 = rn( rn(x2 + z2) + y2 ), rn products
__device__ __forceinline__ float edge_r32(float4 a, float4 b,
                                          float& dx, float& dy, float& dz) {
    dx = minimg(__fsub_rn(a.x, b.x));
    dy = minimg(__fsub_rn(a.y, b.y));
    dz = minimg(__fsub_rn(a.z, b.z));
    float mx = __fmul_rn(dx, dx);
    float my = __fmul_rn(dy, dy);
    float mz = __fmul_rn(dz, dz);
    float r2 = __fadd_rn(__fadd_rn(mx, mz), my);   // (x2+z2)+y2
    return __fsqrt_rn(fmaxf(r2, 1e-24f));
}

// r-grid index/frac, pure f32 rn (frac from the ROUNDED product)
__device__ __forceinline__ void r_interp(float r, float inv_dr, int n_r,
                                         int& idx, int& nxt, float& frac) {
    float rc   = fminf(r, RCLIP_F);
    float idxf = __fmul_rn(rc, inv_dr);
    idx  = (int)idxf;
    frac = __fsub_rn(idxf, (float)idx);
    nxt  = min(idx + 1, n_r - 1);
}

// ---------------------------------------------------------------------------
// K0: pack coords+type, zero scratch, interleave pair tables
__global__ void k_prep(const float* __restrict__ coords,
                       const int*   __restrict__ types,
                       const float* __restrict__ pair,
                       const float* __restrict__ pair_d,
                       int N, int npair) {
    int i = blockIdx.x * blockDim.x + threadIdx.x;
    if (i < N) {
        g_xyzt[i]  = make_float4(coords[3*i], coords[3*i+1], coords[3*i+2],
                                 __int_as_float(types[i]));
        g_force[i] = make_float4(0.f, 0.f, 0.f, 0.f);
        g_rho[i]   = 0.f;
    }
    if (i < npair) g_pair2[i] = make_float2(pair[i], pair_d[i]);
    if (i == 0) { g_acc[0] = 0.0; g_acc[1] = 0.0; }
}

// ---------------------------------------------------------------------------
// K1: density pass — rho[row] += f_{t(col)}(r), rho[col] += f_{t(row)}(r)
__global__ void k_density(const int*   __restrict__ ei,
                          const float* __restrict__ dens,
                          int E, int n_r, float inv_dr) {
    int e = blockIdx.x * blockDim.x + threadIdx.x;
    if (e >= E) return;
    int row = ei[e];
    int col = ei[E + e];
    float4 a = g_xyzt[row];
    float4 b = g_xyzt[col];
    float dx, dy, dz;
    float r = edge_r32(a, b, dx, dy, dz);
    if (!(r < 6.0f)) return;

    int idx, nxt; float frac;
    r_interp(r, inv_dr, n_r, idx, nxt, frac);

    int ti = __float_as_int(a.w);
    int tj = __float_as_int(b.w);
    const float* dj = dens + tj * n_r;
    const float* di = dens + ti * n_r;
    float f_col = lerp_rn(dj[idx], dj[nxt], frac);  // type(col) -> row
    float f_row = lerp_rn(di[idx], di[nxt], frac);  // type(row) -> col

    atomicAdd(&g_rho[row], f_col);
    atomicAdd(&g_rho[col], f_row);
}

// ---------------------------------------------------------------------------
// K2: per-atom embedding F(rho), dF(rho), all f32-rn; accumulate sum F
__global__ void k_embed(const float* __restrict__ emb,
                        const float* __restrict__ emb_d,
                        const float* __restrict__ rho_min,
                        const float* __restrict__ inv_drho,
                        int N, int n_rho) {
    int i = blockIdx.x * blockDim.x + threadIdx.x;
    float F = 0.f;
    if (i < N) {
        int   t    = __float_as_int(g_xyzt[i].w);
        float rho  = g_rho[i];
        float rmin = rho_min[t];
        float invd = inv_drho[t];
        float hi   = __fadd_rn(rmin,
                       __fmul_rn(__fdiv_rn((float)(n_rho - 1), invd), ONE_M_EPS));
        float rc   = fminf(fmaxf(rho, rmin), hi);
        float idxf = __fmul_rn(__fsub_rn(rc, rmin), invd);
        int   idx  = (int)idxf;
        float fr   = __fsub_rn(idxf, (float)idx);
        int   nxt  = min(idx + 1, n_rho - 1);
        const float* et  = emb   + t * n_rho;
        const float* edt = emb_d + t * n_rho;
        F       = lerp_rn(et[idx],  et[nxt],  fr);
        g_dF[i] = lerp_rn(edt[idx], edt[nxt], fr);
    }
    float ws = warp_sum(F);
    __shared__ float sh[8];
    int lane = threadIdx.x & 31, wid = threadIdx.x >> 5;
    if (lane == 0) sh[wid] = ws;
    __syncthreads();
    if (wid == 0) {
        float v = (lane < 8) ? sh[lane] : 0.f;
        v = warp_sum(v);
        if (lane == 0) atomicAdd(&g_acc[0], (double)v);
    }
}

// ---------------------------------------------------------------------------
// K3: force pass — f32-rn values; scatter forces; f64 energy/virial accum
__global__ void k_force(const int*   __restrict__ ei,
                        const float* __restrict__ dens_d,
                        int E, int n_r, int nt, float inv_dr) {
    int e = blockIdx.x * blockDim.x + threadIdx.x;
    double e_loc = 0.0, w_loc = 0.0;
    if (e < E) {
        int row = ei[e];
        int col = ei[E + e];
        float4 a = g_xyzt[row];
        float4 b = g_xyzt[col];
        float dx, dy, dz;
        float r = edge_r32(a, b, dx, dy, dz);
        if (r < 6.0f) {
            int idx, nxt; float frac;
            r_interp(r, inv_dr, n_r, idx, nxt, frac);

            int ti = __float_as_int(a.w);
            int tj = __float_as_int(b.w);

            const float2* pp = g_pair2 + (size_t)(ti * nt + tj) * n_r;
            float2 p0 = pp[idx];
            float2 p1 = pp[nxt];
            float phi  = lerp_rn(p0.x, p1.x, frac);
            float dphi = lerp_rn(p0.y, p1.y, frac);

            const float* ddi = dens_d + ti * n_r;
            const float* ddj = dens_d + tj * n_r;
            float df_i = lerp_rn(ddi[idx], ddi[nxt], frac);
            float df_j = lerp_rn(ddj[idx], ddj[nxt], frac);

            float dFr = g_dF[row];
            float dFc = g_dF[col];
            float coeff = __fadd_rn(__fadd_rn(dphi, __fmul_rn(dFr, df_j)),
                                    __fmul_rn(dFc, df_i));
            float s  = -__fdiv_rn(coeff, r);
            float fx = __fmul_rn(s, dx);
            float fy = __fmul_rn(s, dy);
            float fz = __fmul_rn(s, dz);

            red_add_v4(&g_force[row],  fx,  fy,  fz);
            red_add_v4(&g_force[col], -fx, -fy, -fz);

            e_loc = (double)phi;
            w_loc = (double)__fmul_rn(coeff, r);
        }
    }
    double es  = warp_sumd(e_loc);
    double wsv = warp_sumd(w_loc);
    __shared__ double sh[2][8];
    int lane = threadIdx.x & 31, wid = threadIdx.x >> 5;
    if (lane == 0) { sh[0][wid] = es; sh[1][wid] = wsv; }
    __syncthreads();
    if (wid == 0) {
        double va = (lane < 8) ? sh[0][lane] : 0.0;
        double vb = (lane < 8) ? sh[1][lane] : 0.0;
        va = warp_sumd(va);
        vb = warp_sumd(vb);
        if (lane == 0) {
            atomicAdd(&g_acc[0], va);
            atomicAdd(&g_acc[1], vb);
        }
    }
}

// ---------------------------------------------------------------------------
// K4: finalize — repack forces, write energy + virial
__global__ void k_final(float* __restrict__ out, int N, int out_size) {
    int i = blockIdx.x * blockDim.x + threadIdx.x;
    if (i < N) {
        float4 f = g_force[i];
        out[1 + 3*i + 0] = f.x;
        out[1 + 3*i + 1] = f.y;
        out[1 + 3*i + 2] = f.z;
    }
    if (i == 0) {
        out[0]            = (float)g_acc[0];
        out[out_size - 1] = (float)(-0.5 * g_acc[1]);
    }
}

// ---------------------------------------------------------------------------
extern "C" void kernel_launch(void* const* d_in, const int* in_sizes, int n_in,
                              void* d_out, int out_size) {
    const float* coords  = (const float*)d_in[0];
    const int*   ei      = (const int*)  d_in[1];
    const int*   types   = (const int*)  d_in[2];
    const float* dens    = (const float*)d_in[3];
    const float* dens_d  = (const float*)d_in[4];
    const float* pair    = (const float*)d_in[5];
    const float* pair_d  = (const float*)d_in[6];
    const float* emb     = (const float*)d_in[7];
    const float* emb_d   = (const float*)d_in[8];
    const float* rho_min = (const float*)d_in[9];
    const float* inv_dr  = (const float*)d_in[10];

    int N     = in_sizes[0] / 3;
    int E     = in_sizes[1] / 2;
    int NT    = in_sizes[9];
    int n_r   = in_sizes[3] / NT;
    int n_rho = in_sizes[7] / NT;
    int npair = NT * NT * n_r;

    // reference: inv_dr computed in f64 (python), demoted at the f32 multiply
    float inv_dr_r = (float)((double)(n_r - 1) / 6.0);

    const int TB = 256;
    int prep_items = (N > npair) ? N : npair;

    k_prep   <<<(prep_items + TB - 1) / TB, TB>>>(coords, types, pair, pair_d, N, npair);
    k_density<<<(E + TB - 1) / TB, TB>>>(ei, dens, E, n_r, inv_dr_r);
    k_embed  <<<(N + TB - 1) / TB, TB>>>(emb, emb_d, rho_min, inv_dr, N, n_rho);
    k_force  <<<(E + TB - 1) / TB, TB>>>(ei, dens_d, E, n_r, NT, inv_dr_r);
    k_final  <<<(N + TB - 1) / TB, TB>>>((float*)d_out, N, out_size);
}

// round 17
// speedup vs baseline: 1.0301x; 1.0301x over previous
#include <cuda_runtime.h>
#include <cstdint>

// ---------------------------------------------------------------------------
// EAM energy/forces/virial.  PASSING baseline R15 = 154.2us, rel_err 4.9e-6.
//
// Numerics (FROZEN — do not touch): reference r^2 = rn(rn(x2+z2)+y2) with
// rounded products (XLA:CPU SIMD split-half reduce); all other ops f32-rn,
// no FMA; IEEE sqrt/div; mask r<6; frac from rounded product; f64 output
// accumulators.
//
// R16/R17 perf change: table-layout fusion only (bit-identical values).
//  - g_pairq: {pair, pair_d, dens_d[ti], dens_d[tj]} per (ti,tj,k) ->
//    k_force table loads 6 -> 2 (float4).
//  - g_densp: {dens[tj], dens[ti]} per (ti,tj,k) ->
//    k_density table loads 4 -> 2 (float2).
// (R16 bench was an infra failure — container died; identical resubmit.)
// ---------------------------------------------------------------------------

#define MAXN     100000
#define MAXPAIR  (2 * 2 * 8192)

#define RCLIP_F   ((float)(6.0 * (1.0 - 1e-7)))
#define ONE_M_EPS ((float)(1.0 - 1e-7))

// Scratch (__device__ globals; no allocations allowed)
__device__ float4 g_xyzt[MAXN];      // x,y,z, type-as-bits
__device__ float4 g_force[MAXN];     // accumulated forces (w unused)
__device__ float  g_rho[MAXN];
__device__ float  g_dF[MAXN];
__device__ float4 g_pairq[MAXPAIR];  // {pair, pair_d, dd[ti], dd[tj]}
__device__ float2 g_densp[MAXPAIR];  // {dens[tj], dens[ti]}
__device__ double g_acc[2];          // [0]=energy, [1]=sum coeff*r

// ---------------------------------------------------------------------------
__device__ __forceinline__ float warp_sum(float v) {
#pragma unroll
    for (int o = 16; o > 0; o >>= 1) v += __shfl_down_sync(0xffffffffu, v, o);
    return v;
}

__device__ __forceinline__ double warp_sumd(double v) {
#pragma unroll
    for (int o = 16; o > 0; o >>= 1) v += __shfl_down_sync(0xffffffffu, v, o);
    return v;
}

__device__ __forceinline__ void red_add_v4(float4* p, float x, float y, float z) {
    asm volatile("red.global.add.v4.f32 [%0], {%1, %2, %3, %4};"
                 :: "l"(p), "f"(x), "f"(y), "f"(z), "f"(0.0f) : "memory");
}

// f32 IEEE lerp, no FMA contraction:  a + f*(b-a)
__device__ __forceinline__ float lerp_rn(float a, float b, float f) {
    return __fadd_rn(a, __fmul_rn(f, __fsub_rn(b, a)));
}

// minimum-image:  d - rint(d/10)*10
__device__ __forceinline__ float minimg(float d) {
    float t = rintf(__fdiv_rn(d, 10.0f));
    return __fsub_rn(d, __fmul_rn(t, 10.0f));
}

// FROZEN association:  r2 = rn( rn(x2 + z2) + y2 ), rounded products
__device__ __forceinline__ float edge_r32(float4 a, float4 b,
                                          float& dx, float& dy, float& dz) {
    dx = minimg(__fsub_rn(a.x, b.x));
    dy = minimg(__fsub_rn(a.y, b.y));
    dz = minimg(__fsub_rn(a.z, b.z));
    float mx = __fmul_rn(dx, dx);
    float my = __fmul_rn(dy, dy);
    float mz = __fmul_rn(dz, dz);
    float r2 = __fadd_rn(__fadd_rn(mx, mz), my);
    return __fsqrt_rn(fmaxf(r2, 1e-24f));
}

// r-grid index/frac, pure f32 rn
__device__ __forceinline__ void r_interp(float r, float inv_dr, int n_r,
                                         int& idx, int& nxt, float& frac) {
    float rc   = fminf(r, RCLIP_F);
    float idxf = __fmul_rn(rc, inv_dr);
    idx  = (int)idxf;
    frac = __fsub_rn(idxf, (float)idx);
    nxt  = min(idx + 1, n_r - 1);
}

// ---------------------------------------------------------------------------
// K0: pack coords+type, zero scratch, build fused tables
__global__ void k_prep(const float* __restrict__ coords,
                       const int*   __restrict__ types,
                       const float* __restrict__ pair,
                       const float* __restrict__ pair_d,
                       const float* __restrict__ dens,
                       const float* __restrict__ dens_d,
                       int N, int npair, int n_r, int nt) {
    int i = blockIdx.x * blockDim.x + threadIdx.x;
    if (i < N) {
        g_xyzt[i]  = make_float4(coords[3*i], coords[3*i+1], coords[3*i+2],
                                 __int_as_float(types[i]));
        g_force[i] = make_float4(0.f, 0.f, 0.f, 0.f);
        g_rho[i]   = 0.f;
    }
    if (i < npair) {
        int p  = i / n_r;          // ti*nt + tj
        int k  = i - p * n_r;
        int ti = p / nt;
        int tj = p - ti * nt;
        g_pairq[i] = make_float4(pair[i], pair_d[i],
                                 dens_d[ti * n_r + k], dens_d[tj * n_r + k]);
        g_densp[i] = make_float2(dens[tj * n_r + k], dens[ti * n_r + k]);
    }
    if (i == 0) { g_acc[0] = 0.0; g_acc[1] = 0.0; }
}

// ---------------------------------------------------------------------------
// K1: density pass — rho[row] += f_{t(col)}(r), rho[col] += f_{t(row)}(r)
__global__ void k_density(const int* __restrict__ ei,
                          int E, int n_r, int nt, float inv_dr) {
    int e = blockIdx.x * blockDim.x + threadIdx.x;
    if (e >= E) return;
    int row = ei[e];
    int col = ei[E + e];
    float4 a = g_xyzt[row];
    float4 b = g_xyzt[col];
    float dx, dy, dz;
    float r = edge_r32(a, b, dx, dy, dz);
    if (!(r < 6.0f)) return;

    int idx, nxt; float frac;
    r_interp(r, inv_dr, n_r, idx, nxt, frac);

    int ti = __float_as_int(a.w);
    int tj = __float_as_int(b.w);
    const float2* dp = g_densp + (size_t)(ti * nt + tj) * n_r;
    float2 d0 = dp[idx];
    float2 d1 = dp[nxt];
    float f_col = lerp_rn(d0.x, d1.x, frac);  // dens[tj] -> row
    float f_row = lerp_rn(d0.y, d1.y, frac);  // dens[ti] -> col

    atomicAdd(&g_rho[row], f_col);
    atomicAdd(&g_rho[col], f_row);
}

// ---------------------------------------------------------------------------
// K2: per-atom embedding F(rho), dF(rho), all f32-rn; accumulate sum F
__global__ void k_embed(const float* __restrict__ emb,
                        const float* __restrict__ emb_d,
                        const float* __restrict__ rho_min,
                        const float* __restrict__ inv_drho,
                        int N, int n_rho) {
    int i = blockIdx.x * blockDim.x + threadIdx.x;
    float F = 0.f;
    if (i < N) {
        int   t    = __float_as_int(g_xyzt[i].w);
        float rho  = g_rho[i];
        float rmin = rho_min[t];
        float invd = inv_drho[t];
        float hi   = __fadd_rn(rmin,
                       __fmul_rn(__fdiv_rn((float)(n_rho - 1), invd), ONE_M_EPS));
        float rc   = fminf(fmaxf(rho, rmin), hi);
        float idxf = __fmul_rn(__fsub_rn(rc, rmin), invd);
        int   idx  = (int)idxf;
        float fr   = __fsub_rn(idxf, (float)idx);
        int   nxt  = min(idx + 1, n_rho - 1);
        const float* et  = emb   + t * n_rho;
        const float* edt = emb_d + t * n_rho;
        F       = lerp_rn(et[idx],  et[nxt],  fr);
        g_dF[i] = lerp_rn(edt[idx], edt[nxt], fr);
    }
    float ws = warp_sum(F);
    __shared__ float sh[8];
    int lane = threadIdx.x & 31, wid = threadIdx.x >> 5;
    if (lane == 0) sh[wid] = ws;
    __syncthreads();
    if (wid == 0) {
        float v = (lane < 8) ? sh[lane] : 0.f;
        v = warp_sum(v);
        if (lane == 0) atomicAdd(&g_acc[0], (double)v);
    }
}

// ---------------------------------------------------------------------------
// K3: force pass — fused float4 table; scatter forces; f64 accumulators
__global__ void k_force(const int* __restrict__ ei,
                        int E, int n_r, int nt, float inv_dr) {
    int e = blockIdx.x * blockDim.x + threadIdx.x;
    double e_loc = 0.0, w_loc = 0.0;
    if (e < E) {
        int row = ei[e];
        int col = ei[E + e];
        float4 a = g_xyzt[row];
        float4 b = g_xyzt[col];
        float dx, dy, dz;
        float r = edge_r32(a, b, dx, dy, dz);
        if (r < 6.0f) {
            int idx, nxt; float frac;
            r_interp(r, inv_dr, n_r, idx, nxt, frac);

            int ti = __float_as_int(a.w);
            int tj = __float_as_int(b.w);

            // fused table: {phi, dphi, dd[ti], dd[tj]} at idx and nxt
            const float4* pq = g_pairq + (size_t)(ti * nt + tj) * n_r;
            float4 q0 = pq[idx];
            float4 q1 = pq[nxt];
            float phi  = lerp_rn(q0.x, q1.x, frac);
            float dphi = lerp_rn(q0.y, q1.y, frac);
            float df_i = lerp_rn(q0.z, q1.z, frac);   // dens_d[ti]
            float df_j = lerp_rn(q0.w, q1.w, frac);   // dens_d[tj]

            float dFr = g_dF[row];
            float dFc = g_dF[col];
            float coeff = __fadd_rn(__fadd_rn(dphi, __fmul_rn(dFr, df_j)),
                                    __fmul_rn(dFc, df_i));
            float s  = -__fdiv_rn(coeff, r);
            float fx = __fmul_rn(s, dx);
            float fy = __fmul_rn(s, dy);
            float fz = __fmul_rn(s, dz);

            red_add_v4(&g_force[row],  fx,  fy,  fz);
            red_add_v4(&g_force[col], -fx, -fy, -fz);

            e_loc = (double)phi;
            w_loc = (double)__fmul_rn(coeff, r);
        }
    }
    double es  = warp_sumd(e_loc);
    double wsv = warp_sumd(w_loc);
    __shared__ double sh[2][8];
    int lane = threadIdx.x & 31, wid = threadIdx.x >> 5;
    if (lane == 0) { sh[0][wid] = es; sh[1][wid] = wsv; }
    __syncthreads();
    if (wid == 0) {
        double va = (lane < 8) ? sh[0][lane] : 0.0;
        double vb = (lane < 8) ? sh[1][lane] : 0.0;
        va = warp_sumd(va);
        vb = warp_sumd(vb);
        if (lane == 0) {
            atomicAdd(&g_acc[0], va);
            atomicAdd(&g_acc[1], vb);
        }
    }
}

// ---------------------------------------------------------------------------
// K4: finalize — repack forces, write energy + virial
__global__ void k_final(float* __restrict__ out, int N, int out_size) {
    int i = blockIdx.x * blockDim.x + threadIdx.x;
    if (i < N) {
        float4 f = g_force[i];
        out[1 + 3*i + 0] = f.x;
        out[1 + 3*i + 1] = f.y;
        out[1 + 3*i + 2] = f.z;
    }
    if (i == 0) {
        out[0]            = (float)g_acc[0];
        out[out_size - 1] = (float)(-0.5 * g_acc[1]);
    }
}

// ---------------------------------------------------------------------------
extern "C" void kernel_launch(void* const* d_in, const int* in_sizes, int n_in,
                              void* d_out, int out_size) {
    const float* coords  = (const float*)d_in[0];
    const int*   ei      = (const int*)  d_in[1];
    const int*   types   = (const int*)  d_in[2];
    const float* dens    = (const float*)d_in[3];
    const float* dens_d  = (const float*)d_in[4];
    const float* pair    = (const float*)d_in[5];
    const float* pair_d  = (const float*)d_in[6];
    const float* emb     = (const float*)d_in[7];
    const float* emb_d   = (const float*)d_in[8];
    const float* rho_min = (const float*)d_in[9];
    const float* inv_dr  = (const float*)d_in[10];

    int N     = in_sizes[0] / 3;
    int E     = in_sizes[1] / 2;
    int NT    = in_sizes[9];
    int n_r   = in_sizes[3] / NT;
    int n_rho = in_sizes[7] / NT;
    int npair = NT * NT * n_r;

    float inv_dr_r = (float)((double)(n_r - 1) / 6.0);

    const int TB = 256;
    int prep_items = (N > npair) ? N : npair;

    k_prep   <<<(prep_items + TB - 1) / TB, TB>>>(coords, types, pair, pair_d,
                                                  dens, dens_d, N, npair, n_r, NT);
    k_density<<<(E + TB - 1) / TB, TB>>>(ei, E, n_r, NT, inv_dr_r);
    k_embed  <<<(N + TB - 1) / TB, TB>>>(emb, emb_d, rho_min, inv_dr, N, n_rho);
    k_force  <<<(E + TB - 1) / TB, TB>>>(ei, E, n_r, NT, inv_dr_r);
    k_final  <<<(N + TB - 1) / TB, TB>>>((float*)d_out, N, out_size);
}